// round 1
// baseline (speedup 1.0000x reference)
#include <cuda_runtime.h>
#include <cuda_bf16.h>
#include <cstdint>

// Problem constants
#define BB 2
#define LL 4096
#define CC 512
#define HH 8
#define KK 13
#define DH 64
#define RR 6              // K/2
#define NBIAS 25          // 2K-1
#define SCALE 0.125f      // DH^-0.5 = 1/8

#define M_TOTAL (BB * LL)   // 8192 rows per GEMM

// ---------------------------------------------------------------------------
// Scratch (no cudaMalloc allowed): qh, kh, vh, attention output
// ---------------------------------------------------------------------------
__device__ float g_qh[M_TOTAL * CC];
__device__ float g_kh[M_TOTAL * CC];
__device__ float g_vh[M_TOTAL * CC];
__device__ float g_att[M_TOTAL * CC];

// ---------------------------------------------------------------------------
// SGEMM: C[M,512] = A[M,512] @ W[512,512] + bias
// 128x128 block tile, BK=8, 256 threads, 8x8 microtile, float4 smem.
// M, N, K all multiples of tile sizes -> no bounds checks.
// ---------------------------------------------------------------------------
__global__ __launch_bounds__(256, 2)
void sgemm_bias_kernel(const float* __restrict__ A,
                       const float* __restrict__ W,
                       const float* __restrict__ bias,
                       float* __restrict__ C)
{
    __shared__ __align__(16) float As[8][128];
    __shared__ __align__(16) float Bs[8][128];

    const int tid = threadIdx.x;
    const int block_row = blockIdx.y * 128;
    const int block_col = blockIdx.x * 128;

    // A-tile load mapping: 128 rows x 8 k -> 256 threads x float4
    const int a_row  = tid >> 1;          // 0..127
    const int a_koff = (tid & 1) * 4;     // 0 or 4
    // B-tile load mapping: 8 k-rows x 128 cols -> 256 threads x float4
    const int b_krow = tid >> 5;          // 0..7
    const int b_col  = (tid & 31) * 4;    // 0..124

    const int tr = tid >> 4;              // 0..15  (row group)
    const int tc = tid & 15;              // 0..15  (col group)

    float acc[8][8];
#pragma unroll
    for (int i = 0; i < 8; i++)
#pragma unroll
        for (int j = 0; j < 8; j++) acc[i][j] = 0.0f;

    const float* Aptr = A + (size_t)(block_row + a_row) * CC + a_koff;
    const float* Wptr = W + (size_t)b_krow * CC + block_col + b_col;

    for (int k0 = 0; k0 < CC; k0 += 8) {
        // Load A tile (transposed into As[k][m])
        float4 a4 = *reinterpret_cast<const float4*>(Aptr + k0);
        As[a_koff + 0][a_row] = a4.x;
        As[a_koff + 1][a_row] = a4.y;
        As[a_koff + 2][a_row] = a4.z;
        As[a_koff + 3][a_row] = a4.w;
        // Load B tile (natural layout Bs[k][n])
        float4 b4 = *reinterpret_cast<const float4*>(Wptr + (size_t)k0 * CC);
        *reinterpret_cast<float4*>(&Bs[b_krow][b_col]) = b4;
        __syncthreads();

#pragma unroll
        for (int kk = 0; kk < 8; kk++) {
            float4 ar0 = *reinterpret_cast<const float4*>(&As[kk][tr * 8]);
            float4 ar1 = *reinterpret_cast<const float4*>(&As[kk][tr * 8 + 4]);
            float4 br0 = *reinterpret_cast<const float4*>(&Bs[kk][tc * 8]);
            float4 br1 = *reinterpret_cast<const float4*>(&Bs[kk][tc * 8 + 4]);
            float a[8] = {ar0.x, ar0.y, ar0.z, ar0.w, ar1.x, ar1.y, ar1.z, ar1.w};
            float b[8] = {br0.x, br0.y, br0.z, br0.w, br1.x, br1.y, br1.z, br1.w};
#pragma unroll
            for (int i = 0; i < 8; i++)
#pragma unroll
                for (int j = 0; j < 8; j++)
                    acc[i][j] = fmaf(a[i], b[j], acc[i][j]);
        }
        __syncthreads();
    }

    // Epilogue: add bias, write out
    const int out_row0 = block_row + tr * 8;
    const int out_col0 = block_col + tc * 8;
    float bvals[8];
#pragma unroll
    for (int j = 0; j < 8; j++) bvals[j] = bias[out_col0 + j];
#pragma unroll
    for (int i = 0; i < 8; i++) {
        float* crow = C + (size_t)(out_row0 + i) * CC + out_col0;
#pragma unroll
        for (int j = 0; j < 8; j++) crow[j] = acc[i][j] + bvals[j];
    }
}

// ---------------------------------------------------------------------------
// Neighborhood attention: one warp per (b, i, h). Block = 8 warps = all heads
// for one (b, i). Grid = B*L blocks.
// ---------------------------------------------------------------------------
__global__ __launch_bounds__(256)
void natt_kernel(const float* __restrict__ qh,
                 const float* __restrict__ kh,
                 const float* __restrict__ vh,
                 const float* __restrict__ rpb,
                 float* __restrict__ out)
{
    const int bi = blockIdx.x;           // 0..B*L-1
    const int i  = bi & (LL - 1);
    const int h  = threadIdx.x >> 5;     // 0..7
    const int lane = threadIdx.x & 31;

    int start = i - RR;
    if (start < 0) start = 0;
    if (start > LL - KK) start = LL - KK;

    const size_t rowbase = (size_t)bi * CC;           // (b*L + i) * C
    const float* qp = qh + rowbase + h * DH;
    const float q0 = qp[lane] * SCALE;
    const float q1 = qp[lane + 32] * SCALE;

    const size_t nbrbase = ((size_t)(bi - i + start)) * CC + h * DH; // (b*L+start)*C + h*DH

    float s[KK];
#pragma unroll
    for (int k = 0; k < KK; k++) {
        const float* kp = kh + nbrbase + (size_t)k * CC;
        float d = q0 * kp[lane] + q1 * kp[lane + 32];
#pragma unroll
        for (int off = 16; off > 0; off >>= 1)
            d += __shfl_xor_sync(0xffffffffu, d, off);
        s[k] = d + rpb[h * NBIAS + (start + k - i + (KK - 1))];
    }

    // softmax over K=13
    float m = s[0];
#pragma unroll
    for (int k = 1; k < KK; k++) m = fmaxf(m, s[k]);
    float sum = 0.0f;
#pragma unroll
    for (int k = 0; k < KK; k++) { s[k] = __expf(s[k] - m); sum += s[k]; }
    const float inv = 1.0f / sum;

    float o0 = 0.0f, o1 = 0.0f;
#pragma unroll
    for (int k = 0; k < KK; k++) {
        const float* vp = vh + nbrbase + (size_t)k * CC;
        const float p = s[k] * inv;
        o0 = fmaf(p, vp[lane], o0);
        o1 = fmaf(p, vp[lane + 32], o1);
    }

    float* op = out + rowbase + h * DH;
    op[lane]      = o0;
    op[lane + 32] = o1;
}

// ---------------------------------------------------------------------------
// Launch
// Inputs (metadata order): q, k, v, Wq, bq, Wk, bk, Wv, bv, rpb, Wo, bo
// ---------------------------------------------------------------------------
extern "C" void kernel_launch(void* const* d_in, const int* in_sizes, int n_in,
                              void* d_out, int out_size)
{
    const float* q   = (const float*)d_in[0];
    const float* k   = (const float*)d_in[1];
    const float* v   = (const float*)d_in[2];
    const float* Wq  = (const float*)d_in[3];
    const float* bq  = (const float*)d_in[4];
    const float* Wk  = (const float*)d_in[5];
    const float* bk  = (const float*)d_in[6];
    const float* Wv  = (const float*)d_in[7];
    const float* bv  = (const float*)d_in[8];
    const float* rpb = (const float*)d_in[9];
    const float* Wo  = (const float*)d_in[10];
    const float* bo  = (const float*)d_in[11];
    float* out = (float*)d_out;

    float *qh, *kh, *vh, *att;
    cudaGetSymbolAddress((void**)&qh,  g_qh);
    cudaGetSymbolAddress((void**)&kh,  g_kh);
    cudaGetSymbolAddress((void**)&vh,  g_vh);
    cudaGetSymbolAddress((void**)&att, g_att);

    dim3 gemm_grid(CC / 128, M_TOTAL / 128);   // (4, 64)
    sgemm_bias_kernel<<<gemm_grid, 256>>>(q, Wq, bq, qh);
    sgemm_bias_kernel<<<gemm_grid, 256>>>(k, Wk, bk, kh);
    sgemm_bias_kernel<<<gemm_grid, 256>>>(v, Wv, bv, vh);

    natt_kernel<<<M_TOTAL, 256>>>(qh, kh, vh, rpb, att);

    sgemm_bias_kernel<<<gemm_grid, 256>>>(att, Wo, bo, out);
}

// round 2
// speedup vs baseline: 2.8398x; 2.8398x over previous
#include <cuda_runtime.h>
#include <cuda_bf16.h>
#include <cstdint>

// Problem constants
#define BB 2
#define LL 4096
#define CC 512
#define HH 8
#define KK 13
#define DH 64
#define RR 6              // K/2
#define NBIAS 25          // 2K-1
#define SCALE 0.125f      // DH^-0.5

#define M_TOTAL (BB * LL)   // 8192 rows per GEMM

// Smem strides (in floats/uint32) chosen for conflict-free fragment loads
#define AS_STRIDE 20        // 16 k + 4 pad; bank(g*20+t) distinct for all 32 lanes
#define BS_STRIDE 136       // 128 n + 8 pad; bank(t*136+g) = t*8+g distinct

// ---------------------------------------------------------------------------
// Scratch (no cudaMalloc allowed)
// ---------------------------------------------------------------------------
__device__ float g_qh[M_TOTAL * CC];
__device__ float g_kh[M_TOTAL * CC];
__device__ float g_vh[M_TOTAL * CC];
__device__ float g_att[M_TOTAL * CC];

// ---------------------------------------------------------------------------
// TF32 helpers
// ---------------------------------------------------------------------------
__device__ __forceinline__ uint32_t f2tf32(float x) {
    uint32_t r;
    asm("cvt.rna.tf32.f32 %0, %1;" : "=r"(r) : "f"(x));
    return r;
}

__device__ __forceinline__ void mma_tf32(float& c0, float& c1, float& c2, float& c3,
                                         uint32_t a0, uint32_t a1, uint32_t a2, uint32_t a3,
                                         uint32_t b0, uint32_t b1) {
    asm volatile(
        "mma.sync.aligned.m16n8k8.row.col.f32.tf32.tf32.f32 "
        "{%0,%1,%2,%3}, {%4,%5,%6,%7}, {%8,%9}, {%0,%1,%2,%3};"
        : "+f"(c0), "+f"(c1), "+f"(c2), "+f"(c3)
        : "r"(a0), "r"(a1), "r"(a2), "r"(a3), "r"(b0), "r"(b1));
}

// ---------------------------------------------------------------------------
// TF32 tensor-core GEMM: C[M,512] = A[M,512] @ W[512,512] + bias
// Block tile 128x128, BK=16, 256 threads (8 warps, 2x4), warp tile 64x32.
// Double-buffered smem, one __syncthreads per K-step.
// ---------------------------------------------------------------------------
__global__ __launch_bounds__(256, 2)
void tf32_gemm_bias(const float* __restrict__ A,
                    const float* __restrict__ W,
                    const float* __restrict__ bias,
                    float* __restrict__ C)
{
    __shared__ __align__(16) uint32_t As[2][128 * AS_STRIDE];
    __shared__ __align__(16) uint32_t Bs[2][16 * BS_STRIDE];

    const int tid  = threadIdx.x;
    const int warp = tid >> 5;
    const int lane = tid & 31;
    const int g = lane >> 2;          // 0..7 (group)
    const int t = lane & 3;           // 0..3 (thread-in-group)
    const int wm = (warp & 1) * 64;   // warp m offset
    const int wn = (warp >> 1) * 32;  // warp n offset
    const int block_row = blockIdx.y * 128;
    const int block_col = blockIdx.x * 128;

    // Global load mapping: 512 float4 per tile (A and B each); 2 per thread.
    const int fa1 = tid;
    const int fa2 = tid + 256;
    const int a1_row = fa1 >> 2, a1_kq = fa1 & 3;
    const int a2_row = fa2 >> 2, a2_kq = fa2 & 3;
    const int b1_row = fa1 >> 5, b1_cq = fa1 & 31;
    const int b2_row = fa2 >> 5, b2_cq = fa2 & 31;

    const float* Abase = A + (size_t)block_row * CC;
    const float* Wbase = W + block_col;

    float acc[4][4][4];
#pragma unroll
    for (int mi = 0; mi < 4; mi++)
#pragma unroll
        for (int ni = 0; ni < 4; ni++)
#pragma unroll
            for (int r = 0; r < 4; r++) acc[mi][ni][r] = 0.0f;

    float4 av0, av1, bv0, bv1;

    // Prologue: load tile 0
    av0 = *reinterpret_cast<const float4*>(Abase + (size_t)a1_row * CC + a1_kq * 4);
    av1 = *reinterpret_cast<const float4*>(Abase + (size_t)a2_row * CC + a2_kq * 4);
    bv0 = *reinterpret_cast<const float4*>(Wbase + (size_t)b1_row * CC + b1_cq * 4);
    bv1 = *reinterpret_cast<const float4*>(Wbase + (size_t)b2_row * CC + b2_cq * 4);
    {
        uint4 u;
        u.x = f2tf32(av0.x); u.y = f2tf32(av0.y); u.z = f2tf32(av0.z); u.w = f2tf32(av0.w);
        *reinterpret_cast<uint4*>(&As[0][a1_row * AS_STRIDE + a1_kq * 4]) = u;
        u.x = f2tf32(av1.x); u.y = f2tf32(av1.y); u.z = f2tf32(av1.z); u.w = f2tf32(av1.w);
        *reinterpret_cast<uint4*>(&As[0][a2_row * AS_STRIDE + a2_kq * 4]) = u;
        u.x = f2tf32(bv0.x); u.y = f2tf32(bv0.y); u.z = f2tf32(bv0.z); u.w = f2tf32(bv0.w);
        *reinterpret_cast<uint4*>(&Bs[0][b1_row * BS_STRIDE + b1_cq * 4]) = u;
        u.x = f2tf32(bv1.x); u.y = f2tf32(bv1.y); u.z = f2tf32(bv1.z); u.w = f2tf32(bv1.w);
        *reinterpret_cast<uint4*>(&Bs[0][b2_row * BS_STRIDE + b2_cq * 4]) = u;
    }
    __syncthreads();

    const int NT = CC / 16;   // 32 K-tiles
    int cur = 0;

    for (int it = 0; it < NT; ++it) {
        // Prefetch next tile into registers
        if (it + 1 < NT) {
            const float* An = Abase + (it + 1) * 16;
            const float* Wn = Wbase + (size_t)(it + 1) * 16 * CC;
            av0 = *reinterpret_cast<const float4*>(An + (size_t)a1_row * CC + a1_kq * 4);
            av1 = *reinterpret_cast<const float4*>(An + (size_t)a2_row * CC + a2_kq * 4);
            bv0 = *reinterpret_cast<const float4*>(Wn + (size_t)b1_row * CC + b1_cq * 4);
            bv1 = *reinterpret_cast<const float4*>(Wn + (size_t)b2_row * CC + b2_cq * 4);
        }

        // Compute on current buffer
        const uint32_t* as = As[cur];
        const uint32_t* bs = Bs[cur];
#pragma unroll
        for (int k0 = 0; k0 < 16; k0 += 8) {
            uint32_t ar[4][4], br[4][2];
#pragma unroll
            for (int mi = 0; mi < 4; mi++) {
                const int r0 = (wm + mi * 16 + g) * AS_STRIDE;
                const int r8 = r0 + 8 * AS_STRIDE;
                ar[mi][0] = as[r0 + k0 + t];
                ar[mi][1] = as[r8 + k0 + t];
                ar[mi][2] = as[r0 + k0 + t + 4];
                ar[mi][3] = as[r8 + k0 + t + 4];
            }
#pragma unroll
            for (int ni = 0; ni < 4; ni++) {
                const int c0 = wn + ni * 8 + g;
                br[ni][0] = bs[(k0 + t) * BS_STRIDE + c0];
                br[ni][1] = bs[(k0 + t + 4) * BS_STRIDE + c0];
            }
#pragma unroll
            for (int mi = 0; mi < 4; mi++)
#pragma unroll
                for (int ni = 0; ni < 4; ni++)
                    mma_tf32(acc[mi][ni][0], acc[mi][ni][1], acc[mi][ni][2], acc[mi][ni][3],
                             ar[mi][0], ar[mi][1], ar[mi][2], ar[mi][3],
                             br[ni][0], br[ni][1]);
        }

        // Store next tile to the other buffer
        if (it + 1 < NT) {
            const int nxt = cur ^ 1;
            uint4 u;
            u.x = f2tf32(av0.x); u.y = f2tf32(av0.y); u.z = f2tf32(av0.z); u.w = f2tf32(av0.w);
            *reinterpret_cast<uint4*>(&As[nxt][a1_row * AS_STRIDE + a1_kq * 4]) = u;
            u.x = f2tf32(av1.x); u.y = f2tf32(av1.y); u.z = f2tf32(av1.z); u.w = f2tf32(av1.w);
            *reinterpret_cast<uint4*>(&As[nxt][a2_row * AS_STRIDE + a2_kq * 4]) = u;
            u.x = f2tf32(bv0.x); u.y = f2tf32(bv0.y); u.z = f2tf32(bv0.z); u.w = f2tf32(bv0.w);
            *reinterpret_cast<uint4*>(&Bs[nxt][b1_row * BS_STRIDE + b1_cq * 4]) = u;
            u.x = f2tf32(bv1.x); u.y = f2tf32(bv1.y); u.z = f2tf32(bv1.z); u.w = f2tf32(bv1.w);
            *reinterpret_cast<uint4*>(&Bs[nxt][b2_row * BS_STRIDE + b2_cq * 4]) = u;
        }
        __syncthreads();
        cur ^= 1;
    }

    // Epilogue: bias add + store (c0/c1 are adjacent columns -> float2)
#pragma unroll
    for (int mi = 0; mi < 4; mi++) {
        const int row0 = block_row + wm + mi * 16 + g;
#pragma unroll
        for (int ni = 0; ni < 4; ni++) {
            const int col0 = block_col + wn + ni * 8 + t * 2;
            const float2 b2 = *reinterpret_cast<const float2*>(bias + col0);
            float2 o;
            o.x = acc[mi][ni][0] + b2.x;
            o.y = acc[mi][ni][1] + b2.y;
            *reinterpret_cast<float2*>(C + (size_t)row0 * CC + col0) = o;
            o.x = acc[mi][ni][2] + b2.x;
            o.y = acc[mi][ni][3] + b2.y;
            *reinterpret_cast<float2*>(C + (size_t)(row0 + 8) * CC + col0) = o;
        }
    }
}

// ---------------------------------------------------------------------------
// Neighborhood attention: one warp per (b, i, h); block = 8 warps = one (b,i).
// ---------------------------------------------------------------------------
__global__ __launch_bounds__(256)
void natt_kernel(const float* __restrict__ qh,
                 const float* __restrict__ kh,
                 const float* __restrict__ vh,
                 const float* __restrict__ rpb,
                 float* __restrict__ out)
{
    const int bi = blockIdx.x;
    const int i  = bi & (LL - 1);
    const int h  = threadIdx.x >> 5;
    const int lane = threadIdx.x & 31;

    int start = i - RR;
    if (start < 0) start = 0;
    if (start > LL - KK) start = LL - KK;

    const size_t rowbase = (size_t)bi * CC;
    const float* qp = qh + rowbase + h * DH;
    const float q0 = qp[lane] * SCALE;
    const float q1 = qp[lane + 32] * SCALE;

    const size_t nbrbase = ((size_t)(bi - i + start)) * CC + h * DH;

    float s[KK];
#pragma unroll
    for (int k = 0; k < KK; k++) {
        const float* kp = kh + nbrbase + (size_t)k * CC;
        float d = q0 * kp[lane] + q1 * kp[lane + 32];
#pragma unroll
        for (int off = 16; off > 0; off >>= 1)
            d += __shfl_xor_sync(0xffffffffu, d, off);
        s[k] = d + rpb[h * NBIAS + (start + k - i + (KK - 1))];
    }

    float m = s[0];
#pragma unroll
    for (int k = 1; k < KK; k++) m = fmaxf(m, s[k]);
    float sum = 0.0f;
#pragma unroll
    for (int k = 0; k < KK; k++) { s[k] = __expf(s[k] - m); sum += s[k]; }
    const float inv = 1.0f / sum;

    float o0 = 0.0f, o1 = 0.0f;
#pragma unroll
    for (int k = 0; k < KK; k++) {
        const float* vp = vh + nbrbase + (size_t)k * CC;
        const float p = s[k] * inv;
        o0 = fmaf(p, vp[lane], o0);
        o1 = fmaf(p, vp[lane + 32], o1);
    }

    float* op = out + rowbase + h * DH;
    op[lane]      = o0;
    op[lane + 32] = o1;
}

// ---------------------------------------------------------------------------
// Launch. Inputs: q, k, v, Wq, bq, Wk, bk, Wv, bv, rpb, Wo, bo
// ---------------------------------------------------------------------------
extern "C" void kernel_launch(void* const* d_in, const int* in_sizes, int n_in,
                              void* d_out, int out_size)
{
    const float* q   = (const float*)d_in[0];
    const float* k   = (const float*)d_in[1];
    const float* v   = (const float*)d_in[2];
    const float* Wq  = (const float*)d_in[3];
    const float* bq  = (const float*)d_in[4];
    const float* Wk  = (const float*)d_in[5];
    const float* bk  = (const float*)d_in[6];
    const float* Wv  = (const float*)d_in[7];
    const float* bv  = (const float*)d_in[8];
    const float* rpb = (const float*)d_in[9];
    const float* Wo  = (const float*)d_in[10];
    const float* bo  = (const float*)d_in[11];
    float* out = (float*)d_out;

    float *qh, *kh, *vh, *att;
    cudaGetSymbolAddress((void**)&qh,  g_qh);
    cudaGetSymbolAddress((void**)&kh,  g_kh);
    cudaGetSymbolAddress((void**)&vh,  g_vh);
    cudaGetSymbolAddress((void**)&att, g_att);

    dim3 gemm_grid(CC / 128, M_TOTAL / 128);   // (4, 64)
    tf32_gemm_bias<<<gemm_grid, 256>>>(q, Wq, bq, qh);
    tf32_gemm_bias<<<gemm_grid, 256>>>(k, Wk, bk, kh);
    tf32_gemm_bias<<<gemm_grid, 256>>>(v, Wv, bv, vh);

    natt_kernel<<<M_TOTAL, 256>>>(qh, kh, vh, rpb, att);

    tf32_gemm_bias<<<gemm_grid, 256>>>(att, Wo, bo, out);
}

// round 3
// speedup vs baseline: 3.0564x; 1.0763x over previous
#include <cuda_runtime.h>
#include <cuda_bf16.h>
#include <cstdint>

// Problem constants
#define BB 2
#define LL 4096
#define CC 512
#define HH 8
#define KK 13
#define DH 64
#define RR 6              // K/2
#define NBIAS 25          // 2K-1
#define SCALE 0.125f      // DH^-0.5

#define M_TOTAL (BB * LL)   // 8192 rows per GEMM

// Smem strides (floats) chosen for conflict-free fragment loads AND
// 16B-aligned cp.async destinations.
#define AS_STRIDE 20        // 80B/row (16B-aligned); bank(20g+t) covers all 32
#define BS_STRIDE 136       // 544B/row (16B-aligned); bank(8t+g) covers all 32

#define STAGES 3
#define A_STAGE (128 * AS_STRIDE)   // 2560 floats
#define B_STAGE (16 * BS_STRIDE)    // 2176 floats
#define SMEM_FLOATS (STAGES * (A_STAGE + B_STAGE))

// ---------------------------------------------------------------------------
// Scratch (no cudaMalloc allowed)
// ---------------------------------------------------------------------------
__device__ float g_qh[M_TOTAL * CC];
__device__ float g_kh[M_TOTAL * CC];
__device__ float g_vh[M_TOTAL * CC];
__device__ float g_att[M_TOTAL * CC];

// ---------------------------------------------------------------------------
// Helpers
// ---------------------------------------------------------------------------
__device__ __forceinline__ uint32_t f2tf32(float x) {
    uint32_t r;
    asm("cvt.rna.tf32.f32 %0, %1;" : "=r"(r) : "f"(x));
    return r;
}

__device__ __forceinline__ void mma_tf32(float& c0, float& c1, float& c2, float& c3,
                                         uint32_t a0, uint32_t a1, uint32_t a2, uint32_t a3,
                                         uint32_t b0, uint32_t b1) {
    asm volatile(
        "mma.sync.aligned.m16n8k8.row.col.f32.tf32.tf32.f32 "
        "{%0,%1,%2,%3}, {%4,%5,%6,%7}, {%8,%9}, {%0,%1,%2,%3};"
        : "+f"(c0), "+f"(c1), "+f"(c2), "+f"(c3)
        : "r"(a0), "r"(a1), "r"(a2), "r"(a3), "r"(b0), "r"(b1));
}

__device__ __forceinline__ void cp_async16(uint32_t smem_addr, const void* gptr) {
    asm volatile("cp.async.cg.shared.global [%0], [%1], 16;"
                 :: "r"(smem_addr), "l"(gptr));
}
__device__ __forceinline__ void cp_commit() {
    asm volatile("cp.async.commit_group;");
}
template <int N>
__device__ __forceinline__ void cp_wait() {
    asm volatile("cp.async.wait_group %0;" :: "n"(N));
}

// ---------------------------------------------------------------------------
// TF32 tensor-core GEMM with cp.async 3-stage pipeline.
// C[M,512] = A[M,512] @ W[512,512] + bias
// Block tile 128x128, BK=16, 256 threads (8 warps, 2x4), warp tile 64x32.
// Raw fp32 is cp.async'd into smem; cvt.rna.tf32 happens at fragment load.
// ---------------------------------------------------------------------------
__global__ __launch_bounds__(256, 2)
void tf32_gemm_bias(const float* __restrict__ A,
                    const float* __restrict__ W,
                    const float* __restrict__ bias,
                    float* __restrict__ C)
{
    extern __shared__ float smem[];
    float* As = smem;                      // [STAGES][A_STAGE]
    float* Bs = smem + STAGES * A_STAGE;   // [STAGES][B_STAGE]

    const uint32_t as_base = (uint32_t)__cvta_generic_to_shared(As);
    const uint32_t bs_base = (uint32_t)__cvta_generic_to_shared(Bs);

    const int tid  = threadIdx.x;
    const int warp = tid >> 5;
    const int lane = tid & 31;
    const int g = lane >> 2;          // 0..7
    const int t = lane & 3;           // 0..3
    const int wm = (warp & 1) * 64;
    const int wn = (warp >> 1) * 32;
    const int block_row = blockIdx.y * 128;
    const int block_col = blockIdx.x * 128;

    // Per-tile global->smem copy: A = 512 float4, B = 512 float4; 2 each/thread.
    const int a1_row = tid >> 2,        a1_kq = (tid & 3) * 4;
    const int a2_row = (tid + 256) >> 2, a2_kq = ((tid + 256) & 3) * 4;
    const int b1_row = tid >> 5,        b1_cq = (tid & 31) * 4;
    const int b2_row = (tid + 256) >> 5, b2_cq = ((tid + 256) & 31) * 4;

    const float* Abase = A + (size_t)block_row * CC;
    const float* Wbase = W + block_col;

    // Precomputed smem byte offsets within a stage
    const uint32_t sa1 = (uint32_t)(a1_row * AS_STRIDE + a1_kq) * 4u;
    const uint32_t sa2 = (uint32_t)(a2_row * AS_STRIDE + a2_kq) * 4u;
    const uint32_t sb1 = (uint32_t)(b1_row * BS_STRIDE + b1_cq) * 4u;
    const uint32_t sb2 = (uint32_t)(b2_row * BS_STRIDE + b2_cq) * 4u;

    const int NT = CC / 16;   // 32 K-tiles

    // Issue async copy of tile `it` into stage `stg`
    auto issue_tile = [&](int it, int stg) {
        const float* An = Abase + it * 16;
        const float* Wn = Wbase + (size_t)it * 16 * CC;
        const uint32_t a_off = as_base + (uint32_t)stg * (A_STAGE * 4u);
        const uint32_t b_off = bs_base + (uint32_t)stg * (B_STAGE * 4u);
        cp_async16(a_off + sa1, An + (size_t)a1_row * CC + a1_kq);
        cp_async16(a_off + sa2, An + (size_t)a2_row * CC + a2_kq);
        cp_async16(b_off + sb1, Wn + (size_t)b1_row * CC + b1_cq);
        cp_async16(b_off + sb2, Wn + (size_t)b2_row * CC + b2_cq);
        cp_commit();
    };

    float acc[4][4][4];
#pragma unroll
    for (int mi = 0; mi < 4; mi++)
#pragma unroll
        for (int ni = 0; ni < 4; ni++)
#pragma unroll
            for (int r = 0; r < 4; r++) acc[mi][ni][r] = 0.0f;

    // Prologue: 2 tiles in flight
    issue_tile(0, 0);
    issue_tile(1, 1);
    cp_wait<1>();          // tile 0 resident
    __syncthreads();

    int cur = 0;
    for (int it = 0; it < NT; ++it) {
        // Issue tile it+2 into the free stage
        if (it + 2 < NT) {
            int stg = (cur + 2) % STAGES;
            issue_tile(it + 2, stg);
        }

        // Compute on current stage
        const float* asf = As + cur * A_STAGE;
        const float* bsf = Bs + cur * B_STAGE;
#pragma unroll
        for (int k0 = 0; k0 < 16; k0 += 8) {
            uint32_t ar[4][4], br[4][2];
#pragma unroll
            for (int mi = 0; mi < 4; mi++) {
                const int r0 = (wm + mi * 16 + g) * AS_STRIDE;
                const int r8 = r0 + 8 * AS_STRIDE;
                ar[mi][0] = f2tf32(asf[r0 + k0 + t]);
                ar[mi][1] = f2tf32(asf[r8 + k0 + t]);
                ar[mi][2] = f2tf32(asf[r0 + k0 + t + 4]);
                ar[mi][3] = f2tf32(asf[r8 + k0 + t + 4]);
            }
#pragma unroll
            for (int ni = 0; ni < 4; ni++) {
                const int c0 = wn + ni * 8 + g;
                br[ni][0] = f2tf32(bsf[(k0 + t) * BS_STRIDE + c0]);
                br[ni][1] = f2tf32(bsf[(k0 + t + 4) * BS_STRIDE + c0]);
            }
#pragma unroll
            for (int mi = 0; mi < 4; mi++)
#pragma unroll
                for (int ni = 0; ni < 4; ni++)
                    mma_tf32(acc[mi][ni][0], acc[mi][ni][1], acc[mi][ni][2], acc[mi][ni][3],
                             ar[mi][0], ar[mi][1], ar[mi][2], ar[mi][3],
                             br[ni][0], br[ni][1]);
        }

        // Make tile it+1 resident before next iteration
        cp_wait<1>();
        __syncthreads();
        cur = (cur + 1) % STAGES;
    }

    // Epilogue: bias add + store
#pragma unroll
    for (int mi = 0; mi < 4; mi++) {
        const int row0 = block_row + wm + mi * 16 + g;
#pragma unroll
        for (int ni = 0; ni < 4; ni++) {
            const int col0 = block_col + wn + ni * 8 + t * 2;
            const float2 b2 = *reinterpret_cast<const float2*>(bias + col0);
            float2 o;
            o.x = acc[mi][ni][0] + b2.x;
            o.y = acc[mi][ni][1] + b2.y;
            *reinterpret_cast<float2*>(C + (size_t)row0 * CC + col0) = o;
            o.x = acc[mi][ni][2] + b2.x;
            o.y = acc[mi][ni][3] + b2.y;
            *reinterpret_cast<float2*>(C + (size_t)(row0 + 8) * CC + col0) = o;
        }
    }
}

// ---------------------------------------------------------------------------
// Neighborhood attention: one warp per (b, i, h); block = 8 warps = one (b,i).
// (Unchanged this round to isolate the GEMM change.)
// ---------------------------------------------------------------------------
__global__ __launch_bounds__(256)
void natt_kernel(const float* __restrict__ qh,
                 const float* __restrict__ kh,
                 const float* __restrict__ vh,
                 const float* __restrict__ rpb,
                 float* __restrict__ out)
{
    const int bi = blockIdx.x;
    const int i  = bi & (LL - 1);
    const int h  = threadIdx.x >> 5;
    const int lane = threadIdx.x & 31;

    int start = i - RR;
    if (start < 0) start = 0;
    if (start > LL - KK) start = LL - KK;

    const size_t rowbase = (size_t)bi * CC;
    const float* qp = qh + rowbase + h * DH;
    const float q0 = qp[lane] * SCALE;
    const float q1 = qp[lane + 32] * SCALE;

    const size_t nbrbase = ((size_t)(bi - i + start)) * CC + h * DH;

    float s[KK];
#pragma unroll
    for (int k = 0; k < KK; k++) {
        const float* kp = kh + nbrbase + (size_t)k * CC;
        float d = q0 * kp[lane] + q1 * kp[lane + 32];
#pragma unroll
        for (int off = 16; off > 0; off >>= 1)
            d += __shfl_xor_sync(0xffffffffu, d, off);
        s[k] = d + rpb[h * NBIAS + (start + k - i + (KK - 1))];
    }

    float m = s[0];
#pragma unroll
    for (int k = 1; k < KK; k++) m = fmaxf(m, s[k]);
    float sum = 0.0f;
#pragma unroll
    for (int k = 0; k < KK; k++) { s[k] = __expf(s[k] - m); sum += s[k]; }
    const float inv = 1.0f / sum;

    float o0 = 0.0f, o1 = 0.0f;
#pragma unroll
    for (int k = 0; k < KK; k++) {
        const float* vp = vh + nbrbase + (size_t)k * CC;
        const float p = s[k] * inv;
        o0 = fmaf(p, vp[lane], o0);
        o1 = fmaf(p, vp[lane + 32], o1);
    }

    float* op = out + rowbase + h * DH;
    op[lane]      = o0;
    op[lane + 32] = o1;
}

// ---------------------------------------------------------------------------
// Launch. Inputs: q, k, v, Wq, bq, Wk, bk, Wv, bv, rpb, Wo, bo
// ---------------------------------------------------------------------------
extern "C" void kernel_launch(void* const* d_in, const int* in_sizes, int n_in,
                              void* d_out, int out_size)
{
    const float* q   = (const float*)d_in[0];
    const float* k   = (const float*)d_in[1];
    const float* v   = (const float*)d_in[2];
    const float* Wq  = (const float*)d_in[3];
    const float* bq  = (const float*)d_in[4];
    const float* Wk  = (const float*)d_in[5];
    const float* bk  = (const float*)d_in[6];
    const float* Wv  = (const float*)d_in[7];
    const float* bv  = (const float*)d_in[8];
    const float* rpb = (const float*)d_in[9];
    const float* Wo  = (const float*)d_in[10];
    const float* bo  = (const float*)d_in[11];
    float* out = (float*)d_out;

    float *qh, *kh, *vh, *att;
    cudaGetSymbolAddress((void**)&qh,  g_qh);
    cudaGetSymbolAddress((void**)&kh,  g_kh);
    cudaGetSymbolAddress((void**)&vh,  g_vh);
    cudaGetSymbolAddress((void**)&att, g_att);

    const int smem_bytes = SMEM_FLOATS * 4;   // ~55.5 KB
    cudaFuncSetAttribute(tf32_gemm_bias,
                         cudaFuncAttributeMaxDynamicSharedMemorySize, smem_bytes);

    dim3 gemm_grid(CC / 128, M_TOTAL / 128);   // (4, 64)
    tf32_gemm_bias<<<gemm_grid, 256, smem_bytes>>>(q, Wq, bq, qh);
    tf32_gemm_bias<<<gemm_grid, 256, smem_bytes>>>(k, Wk, bk, kh);
    tf32_gemm_bias<<<gemm_grid, 256, smem_bytes>>>(v, Wv, bv, vh);

    natt_kernel<<<M_TOTAL, 256>>>(qh, kh, vh, rpb, att);

    tf32_gemm_bias<<<gemm_grid, 256, smem_bytes>>>(att, Wo, bo, out);
}

// round 5
// speedup vs baseline: 3.2697x; 1.0698x over previous
#include <cuda_runtime.h>
#include <cuda_bf16.h>
#include <cstdint>

// Problem constants
#define BB 2
#define LL 4096
#define CC 512
#define HH 8
#define KK 13
#define DH 64
#define RR 6              // K/2
#define NBIAS 25          // 2K-1
#define SCALE 0.125f      // DH^-0.5

#define M_TOTAL (BB * LL)   // 8192 rows per GEMM

// Smem strides (floats): conflict-free fragment loads + 16B-aligned cp.async dsts
#define AS_STRIDE 20
#define BS_STRIDE 136

#define STAGES 3
#define A_STAGE (128 * AS_STRIDE)
#define B_STAGE (16 * BS_STRIDE)
#define SMEM_FLOATS (STAGES * (A_STAGE + B_STAGE))

// ---------------------------------------------------------------------------
// Scratch (no cudaMalloc allowed)
// ---------------------------------------------------------------------------
__device__ float g_qh[M_TOTAL * CC];
__device__ float g_kh[M_TOTAL * CC];
__device__ float g_vh[M_TOTAL * CC];
__device__ float g_att[M_TOTAL * CC];

// ---------------------------------------------------------------------------
// Helpers
// ---------------------------------------------------------------------------
__device__ __forceinline__ uint32_t f2tf32(float x) {
    uint32_t r;
    asm("cvt.rna.tf32.f32 %0, %1;" : "=r"(r) : "f"(x));
    return r;
}

__device__ __forceinline__ void mma_tf32(float& c0, float& c1, float& c2, float& c3,
                                         uint32_t a0, uint32_t a1, uint32_t a2, uint32_t a3,
                                         uint32_t b0, uint32_t b1) {
    asm volatile(
        "mma.sync.aligned.m16n8k8.row.col.f32.tf32.tf32.f32 "
        "{%0,%1,%2,%3}, {%4,%5,%6,%7}, {%8,%9}, {%0,%1,%2,%3};"
        : "+f"(c0), "+f"(c1), "+f"(c2), "+f"(c3)
        : "r"(a0), "r"(a1), "r"(a2), "r"(a3), "r"(b0), "r"(b1));
}

__device__ __forceinline__ void cp_async16(uint32_t smem_addr, const void* gptr) {
    asm volatile("cp.async.cg.shared.global [%0], [%1], 16;"
                 :: "r"(smem_addr), "l"(gptr));
}
__device__ __forceinline__ void cp_commit() {
    asm volatile("cp.async.commit_group;");
}
template <int N>
__device__ __forceinline__ void cp_wait() {
    asm volatile("cp.async.wait_group %0;" :: "n"(N));
}

// ---------------------------------------------------------------------------
// TF32 tensor-core GEMM body (legacy mma.sync path — baseline PTX ISA).
// C[M,512] = A[M,512] @ W[512,512] + bias
// Block tile 128x128, BK=16, 256 threads (8 warps, 2x4), warp tile 64x32.
// cp.async 3-stage pipeline; cvt.rna.tf32 at fragment-load time.
// ---------------------------------------------------------------------------
__device__ __forceinline__
void gemm_body(const float* __restrict__ A,
               const float* __restrict__ W,
               const float* __restrict__ bias,
               float* __restrict__ C)
{
    extern __shared__ float smem[];
    float* As = smem;
    float* Bs = smem + STAGES * A_STAGE;

    const uint32_t as_base = (uint32_t)__cvta_generic_to_shared(As);
    const uint32_t bs_base = (uint32_t)__cvta_generic_to_shared(Bs);

    const int tid  = threadIdx.x;
    const int warp = tid >> 5;
    const int lane = tid & 31;
    const int g = lane >> 2;
    const int t = lane & 3;
    const int wm = (warp & 1) * 64;
    const int wn = (warp >> 1) * 32;
    const int block_row = blockIdx.y * 128;
    const int block_col = blockIdx.x * 128;

    const int a1_row = tid >> 2,         a1_kq = (tid & 3) * 4;
    const int a2_row = (tid + 256) >> 2, a2_kq = ((tid + 256) & 3) * 4;
    const int b1_row = tid >> 5,         b1_cq = (tid & 31) * 4;
    const int b2_row = (tid + 256) >> 5, b2_cq = ((tid + 256) & 31) * 4;

    const float* Abase = A + (size_t)block_row * CC;
    const float* Wbase = W + block_col;

    const uint32_t sa1 = (uint32_t)(a1_row * AS_STRIDE + a1_kq) * 4u;
    const uint32_t sa2 = (uint32_t)(a2_row * AS_STRIDE + a2_kq) * 4u;
    const uint32_t sb1 = (uint32_t)(b1_row * BS_STRIDE + b1_cq) * 4u;
    const uint32_t sb2 = (uint32_t)(b2_row * BS_STRIDE + b2_cq) * 4u;

    const int NT = CC / 16;

    auto issue_tile = [&](int it, int stg) {
        const float* An = Abase + it * 16;
        const float* Wn = Wbase + (size_t)it * 16 * CC;
        const uint32_t a_off = as_base + (uint32_t)stg * (A_STAGE * 4u);
        const uint32_t b_off = bs_base + (uint32_t)stg * (B_STAGE * 4u);
        cp_async16(a_off + sa1, An + (size_t)a1_row * CC + a1_kq);
        cp_async16(a_off + sa2, An + (size_t)a2_row * CC + a2_kq);
        cp_async16(b_off + sb1, Wn + (size_t)b1_row * CC + b1_cq);
        cp_async16(b_off + sb2, Wn + (size_t)b2_row * CC + b2_cq);
        cp_commit();
    };

    float acc[4][4][4];
#pragma unroll
    for (int mi = 0; mi < 4; mi++)
#pragma unroll
        for (int ni = 0; ni < 4; ni++)
#pragma unroll
            for (int r = 0; r < 4; r++) acc[mi][ni][r] = 0.0f;

    issue_tile(0, 0);
    issue_tile(1, 1);
    cp_wait<1>();
    __syncthreads();

    int cur = 0;
    for (int it = 0; it < NT; ++it) {
        if (it + 2 < NT) issue_tile(it + 2, (cur + 2) % STAGES);

        const float* asf = As + cur * A_STAGE;
        const float* bsf = Bs + cur * B_STAGE;
#pragma unroll
        for (int k0 = 0; k0 < 16; k0 += 8) {
            uint32_t ar[4][4], br[4][2];
#pragma unroll
            for (int mi = 0; mi < 4; mi++) {
                const int r0 = (wm + mi * 16 + g) * AS_STRIDE;
                const int r8 = r0 + 8 * AS_STRIDE;
                ar[mi][0] = f2tf32(asf[r0 + k0 + t]);
                ar[mi][1] = f2tf32(asf[r8 + k0 + t]);
                ar[mi][2] = f2tf32(asf[r0 + k0 + t + 4]);
                ar[mi][3] = f2tf32(asf[r8 + k0 + t + 4]);
            }
#pragma unroll
            for (int ni = 0; ni < 4; ni++) {
                const int c0 = wn + ni * 8 + g;
                br[ni][0] = f2tf32(bsf[(k0 + t) * BS_STRIDE + c0]);
                br[ni][1] = f2tf32(bsf[(k0 + t + 4) * BS_STRIDE + c0]);
            }
#pragma unroll
            for (int mi = 0; mi < 4; mi++)
#pragma unroll
                for (int ni = 0; ni < 4; ni++)
                    mma_tf32(acc[mi][ni][0], acc[mi][ni][1], acc[mi][ni][2], acc[mi][ni][3],
                             ar[mi][0], ar[mi][1], ar[mi][2], ar[mi][3],
                             br[ni][0], br[ni][1]);
        }

        cp_wait<1>();
        __syncthreads();
        cur = (cur + 1) % STAGES;
    }

#pragma unroll
    for (int mi = 0; mi < 4; mi++) {
        const int row0 = block_row + wm + mi * 16 + g;
#pragma unroll
        for (int ni = 0; ni < 4; ni++) {
            const int col0 = block_col + wn + ni * 8 + t * 2;
            const float2 b2 = *reinterpret_cast<const float2*>(bias + col0);
            float2 o;
            o.x = acc[mi][ni][0] + b2.x;
            o.y = acc[mi][ni][1] + b2.y;
            *reinterpret_cast<float2*>(C + (size_t)row0 * CC + col0) = o;
            o.x = acc[mi][ni][2] + b2.x;
            o.y = acc[mi][ni][3] + b2.y;
            *reinterpret_cast<float2*>(C + (size_t)(row0 + 8) * CC + col0) = o;
        }
    }
}

// Batched QKV: blockIdx.z selects (A, W, bias, C) triple
__global__ __launch_bounds__(256, 2)
void tf32_gemm_qkv(const float* __restrict__ q, const float* __restrict__ k,
                   const float* __restrict__ v,
                   const float* __restrict__ Wq, const float* __restrict__ Wk,
                   const float* __restrict__ Wv,
                   const float* __restrict__ bq, const float* __restrict__ bk,
                   const float* __restrict__ bv,
                   float* __restrict__ qh, float* __restrict__ kh,
                   float* __restrict__ vh)
{
    const int z = blockIdx.z;
    const float* A    = (z == 0) ? q  : (z == 1) ? k  : v;
    const float* W    = (z == 0) ? Wq : (z == 1) ? Wk : Wv;
    const float* bias = (z == 0) ? bq : (z == 1) ? bk : bv;
    float*       C    = (z == 0) ? qh : (z == 1) ? kh : vh;
    gemm_body(A, W, bias, C);
}

__global__ __launch_bounds__(256, 2)
void tf32_gemm_bias(const float* __restrict__ A, const float* __restrict__ W,
                    const float* __restrict__ bias, float* __restrict__ C)
{
    gemm_body(A, W, bias, C);
}

// ---------------------------------------------------------------------------
// Neighborhood attention, vectorized.
// Lane layout: qi = lane>>3 (4 queries/warp), d8 = (lane&7)*8 (8 dims/lane).
// Warp = one head, 4 consecutive queries. Block = 8 warps = 8 heads.
// Dot reduction = 3-step butterfly within the 8-lane dim-group.
// ---------------------------------------------------------------------------
__global__ __launch_bounds__(256)
void natt_kernel(const float* __restrict__ qh,
                 const float* __restrict__ kh,
                 const float* __restrict__ vh,
                 const float* __restrict__ rpb,
                 float* __restrict__ out)
{
    const int bi0  = blockIdx.x * 4;          // 4 queries per block
    const int h    = threadIdx.x >> 5;        // warp = head
    const int lane = threadIdx.x & 31;
    const int qi   = lane >> 3;
    const int d8   = (lane & 7) * 8;

    const int bi = bi0 + qi;
    const int i  = bi & (LL - 1);

    int start = i - RR;
    if (start < 0) start = 0;
    if (start > LL - KK) start = LL - KK;

    const size_t qoff = (size_t)bi * CC + h * DH + d8;
    float4 qa = *reinterpret_cast<const float4*>(qh + qoff);
    float4 qb = *reinterpret_cast<const float4*>(qh + qoff + 4);
    qa.x *= SCALE; qa.y *= SCALE; qa.z *= SCALE; qa.w *= SCALE;
    qb.x *= SCALE; qb.y *= SCALE; qb.z *= SCALE; qb.w *= SCALE;

    // (b*L + start) * C + head/dim offset
    const size_t nbase = (size_t)(bi - i + start) * CC + h * DH + d8;
    const int bias_off = h * NBIAS + (start - i + (KK - 1));

    float s[KK];
#pragma unroll
    for (int k = 0; k < KK; k++) {
        const float* kp = kh + nbase + (size_t)k * CC;
        const float4 ka = *reinterpret_cast<const float4*>(kp);
        const float4 kb = *reinterpret_cast<const float4*>(kp + 4);
        float d = qa.x * ka.x + qa.y * ka.y + qa.z * ka.z + qa.w * ka.w
                + qb.x * kb.x + qb.y * kb.y + qb.z * kb.z + qb.w * kb.w;
        d += __shfl_xor_sync(0xffffffffu, d, 1);
        d += __shfl_xor_sync(0xffffffffu, d, 2);
        d += __shfl_xor_sync(0xffffffffu, d, 4);
        s[k] = d + rpb[bias_off + k];
    }

    // softmax over K=13 (replicated across the 8 lanes of the group)
    float m = s[0];
#pragma unroll
    for (int k = 1; k < KK; k++) m = fmaxf(m, s[k]);
    float sum = 0.0f;
#pragma unroll
    for (int k = 0; k < KK; k++) { s[k] = __expf(s[k] - m); sum += s[k]; }
    const float inv = 1.0f / sum;

    float4 oa = make_float4(0.f, 0.f, 0.f, 0.f);
    float4 ob = make_float4(0.f, 0.f, 0.f, 0.f);
#pragma unroll
    for (int k = 0; k < KK; k++) {
        const float* vp = vh + nbase + (size_t)k * CC;
        const float4 va = *reinterpret_cast<const float4*>(vp);
        const float4 vb = *reinterpret_cast<const float4*>(vp + 4);
        const float p = s[k] * inv;
        oa.x = fmaf(p, va.x, oa.x); oa.y = fmaf(p, va.y, oa.y);
        oa.z = fmaf(p, va.z, oa.z); oa.w = fmaf(p, va.w, oa.w);
        ob.x = fmaf(p, vb.x, ob.x); ob.y = fmaf(p, vb.y, ob.y);
        ob.z = fmaf(p, vb.z, ob.z); ob.w = fmaf(p, vb.w, ob.w);
    }

    *reinterpret_cast<float4*>(out + qoff)     = oa;
    *reinterpret_cast<float4*>(out + qoff + 4) = ob;
}

// ---------------------------------------------------------------------------
// Launch. Inputs: q, k, v, Wq, bq, Wk, bk, Wv, bv, rpb, Wo, bo
// ---------------------------------------------------------------------------
extern "C" void kernel_launch(void* const* d_in, const int* in_sizes, int n_in,
                              void* d_out, int out_size)
{
    const float* q   = (const float*)d_in[0];
    const float* k   = (const float*)d_in[1];
    const float* v   = (const float*)d_in[2];
    const float* Wq  = (const float*)d_in[3];
    const float* bq  = (const float*)d_in[4];
    const float* Wk  = (const float*)d_in[5];
    const float* bk  = (const float*)d_in[6];
    const float* Wv  = (const float*)d_in[7];
    const float* bv  = (const float*)d_in[8];
    const float* rpb = (const float*)d_in[9];
    const float* Wo  = (const float*)d_in[10];
    const float* bo  = (const float*)d_in[11];
    float* out = (float*)d_out;

    float *qh, *kh, *vh, *att;
    cudaGetSymbolAddress((void**)&qh,  g_qh);
    cudaGetSymbolAddress((void**)&kh,  g_kh);
    cudaGetSymbolAddress((void**)&vh,  g_vh);
    cudaGetSymbolAddress((void**)&att, g_att);

    const int smem_bytes = SMEM_FLOATS * 4;   // ~55.5 KB
    cudaFuncSetAttribute(tf32_gemm_qkv,
                         cudaFuncAttributeMaxDynamicSharedMemorySize, smem_bytes);
    cudaFuncSetAttribute(tf32_gemm_bias,
                         cudaFuncAttributeMaxDynamicSharedMemorySize, smem_bytes);

    dim3 qkv_grid(CC / 128, M_TOTAL / 128, 3);   // (4, 64, 3)
    tf32_gemm_qkv<<<qkv_grid, 256, smem_bytes>>>(q, k, v, Wq, Wk, Wv,
                                                 bq, bk, bv, qh, kh, vh);

    natt_kernel<<<M_TOTAL / 4, 256>>>(qh, kh, vh, rpb, att);

    dim3 gemm_grid(CC / 128, M_TOTAL / 128);     // (4, 64)
    tf32_gemm_bias<<<gemm_grid, 256, smem_bytes>>>(att, Wo, bo, out);
}